// round 17
// baseline (speedup 1.0000x reference)
#include <cuda_runtime.h>
#include <cuda_bf16.h>
#include <math_constants.h>
#include <mma.h>
#include <cstdint>

using namespace nvcuda;

#define Bk 8
#define Nk 1024
#define Ck 256
#define Hk 4
#define Dk 64

#define OUT_ELEMS (Bk * Nk * Ck)      /* 2097152 : p_attn starts after this   */

#define LDT 72                        /* bf16 tile ld: 64 + 8 pad             */

// precomputed bf16 split operands (static scratch — allowed)
__device__ __nv_bfloat16 g_qhi[OUT_ELEMS];
__device__ __nv_bfloat16 g_qlo[OUT_ELEMS];
__device__ __nv_bfloat16 g_khi[OUT_ELEMS];
__device__ __nv_bfloat16 g_klo[OUT_ELEMS];
__device__ __nv_bfloat16 g_vhi[OUT_ELEMS];
__device__ __nv_bfloat16 g_vlo[OUT_ELEMS];

// ---------------------------------------------------------------------------
// One-shot fp32 -> (hi, lo) bf16 split for q, k, v in a single launch.
// grid = (OUT_ELEMS/4/256, 3); y picks the tensor.
// ---------------------------------------------------------------------------
__global__ __launch_bounds__(256) void k_cvt_all(
    const float* __restrict__ q, const float* __restrict__ k,
    const float* __restrict__ v)
{
    const int i4 = blockIdx.x * 256 + threadIdx.x;          // float4 index
    if (i4 >= OUT_ELEMS / 4) return;
    const int which = blockIdx.y;
    const float* src = which == 0 ? q : (which == 1 ? k : v);
    __nv_bfloat16* hi = which == 0 ? g_qhi : (which == 1 ? g_khi : g_vhi);
    __nv_bfloat16* lo = which == 0 ? g_qlo : (which == 1 ? g_klo : g_vlo);

    float4 val = ((const float4*)src)[i4];
    __nv_bfloat16 hx = __float2bfloat16(val.x);
    __nv_bfloat16 hy = __float2bfloat16(val.y);
    __nv_bfloat16 hz = __float2bfloat16(val.z);
    __nv_bfloat16 hw = __float2bfloat16(val.w);
    __nv_bfloat162 h01(hx, hy), h23(hz, hw);
    __nv_bfloat162 l01(__float2bfloat16(val.x - __bfloat162float(hx)),
                       __float2bfloat16(val.y - __bfloat162float(hy)));
    __nv_bfloat162 l23(__float2bfloat16(val.z - __bfloat162float(hz)),
                       __float2bfloat16(val.w - __bfloat162float(hw)));
    uint2 hp = make_uint2(*(uint32_t*)&h01, *(uint32_t*)&h23);
    uint2 lp = make_uint2(*(uint32_t*)&l01, *(uint32_t*)&l23);
    ((uint2*)hi)[i4] = hp;
    ((uint2*)lo)[i4] = lp;
}

// ===========================================================================
// Kernel 1 (WMMA bf16 split-3): raw S = QK^T only. Tile 64x64, 128 threads,
// 4 warps (warp w = rows 16w..16w+15), acc[4]. Fragments stored directly to
// gmem with ld=Nk — no smem staging, no epilogue. Low regs -> high occupancy.
// ===========================================================================
#define QK_QHI 0
#define QK_QLO 9216
#define QK_KHI 18432
#define QK_KLO 27648
#define QK_TOTAL 36864

__global__ __launch_bounds__(128) void k_qk(float* __restrict__ S)
{
    extern __shared__ char sm[];
    __nv_bfloat16* Qhi = (__nv_bfloat16*)(sm + QK_QHI);
    __nv_bfloat16* Qlo = (__nv_bfloat16*)(sm + QK_QLO);
    __nv_bfloat16* Khi = (__nv_bfloat16*)(sm + QK_KHI);
    __nv_bfloat16* Klo = (__nv_bfloat16*)(sm + QK_KLO);

    const int n0 = blockIdx.x * 64;
    const int m0 = blockIdx.y * 64;
    const int z  = blockIdx.z;         // h*8 + b
    const int h  = z >> 3;
    const int b  = z & 7;
    const int tid = threadIdx.x;
    const int wid = tid >> 5;

    // fill: 64 rows x 8 uint4 per plane (pure copies of precomputed bf16)
    for (int idx = tid; idx < 64 * 8; idx += 128) {
        const int r = idx >> 3;
        const int u = idx & 7;
        const size_t gq = ((size_t)b * Nk + n0 + r) * Ck + h * Dk + u * 8;
        const size_t gk = ((size_t)b * Nk + m0 + r) * Ck + h * Dk + u * 8;
        *(uint4*)(Qhi + r * LDT + u * 8) = *(const uint4*)(g_qhi + gq);
        *(uint4*)(Qlo + r * LDT + u * 8) = *(const uint4*)(g_qlo + gq);
        *(uint4*)(Khi + r * LDT + u * 8) = *(const uint4*)(g_khi + gk);
        *(uint4*)(Klo + r * LDT + u * 8) = *(const uint4*)(g_klo + gk);
    }
    __syncthreads();

    wmma::fragment<wmma::accumulator, 16, 16, 16, float> acc[4];
#pragma unroll
    for (int nt = 0; nt < 4; nt++) wmma::fill_fragment(acc[nt], 0.0f);

    const __nv_bfloat16* Ab[3] = {Qhi, Qhi, Qlo};
    const __nv_bfloat16* Bb[3] = {Khi, Klo, Khi};
#pragma unroll
    for (int p = 0; p < 3; p++) {
#pragma unroll
        for (int kt = 0; kt < 4; kt++) {
            wmma::fragment<wmma::matrix_a, 16, 16, 16, __nv_bfloat16, wmma::row_major> a;
            wmma::load_matrix_sync(a, Ab[p] + (wid * 16) * LDT + kt * 16, LDT);
#pragma unroll
            for (int nt = 0; nt < 4; nt++) {
                wmma::fragment<wmma::matrix_b, 16, 16, 16, __nv_bfloat16, wmma::col_major> bf;
                wmma::load_matrix_sync(bf, Bb[p] + (nt * 16) * LDT + kt * 16, LDT);
                wmma::mma_sync(acc[nt], a, bf, acc[nt]);
            }
        }
    }

    // direct store to gmem, ld = Nk
    float* Srow = S + ((size_t)z * Nk + n0 + wid * 16) * Nk + m0;
#pragma unroll
    for (int nt = 0; nt < 4; nt++)
        wmma::store_matrix_sync(Srow + nt * 16, acc[nt], Nk, wmma::mem_row_major);
}

// ---------------------------------------------------------------------------
// Kernel 2 (fused): s = (S + dis)/8; mask -> -inf; softmax; write P in place.
// One block per row (256 threads, 4 elems each). Mask dtype detected inline
// from its first 16 words (L2-cached; uniform per block).
// ---------------------------------------------------------------------------
__global__ __launch_bounds__(256) void k_softmax_f(
    float* __restrict__ P, const float* __restrict__ dis,
    const void* __restrict__ mask)
{
    __shared__ float redm[8];
    __shared__ float reds[8];

    const int row = blockIdx.x;        // [0, 32768)
    const int n   = row & (Nk - 1);
    const int z   = row >> 10;         // h*8 + b
    const int b   = z & 7;
    const int tid = threadIdx.x;

    // mask dtype: 1 = int32 (words all 0/1), 2 = float32 (0 / 0x3F800000), 0 = uint8
    const unsigned int* mw = (const unsigned int*)mask;
    int i32ok = 1, f32ok = 1;
#pragma unroll
    for (int i = 0; i < 16; i++) {
        unsigned int x = mw[i];
        if (x != 0u && x != 1u)           i32ok = 0;
        if (x != 0u && x != 0x3F800000u)  f32ok = 0;
    }
    const int kind = i32ok ? 1 : (f32ok ? 2 : 0);

    const size_t prow = (size_t)row * Nk;
    const size_t drow = ((size_t)b * Nk + n) * Nk;

    float4 v = *(float4*)(P + prow + tid * 4);
    float4 dv = *(const float4*)(dis + drow + tid * 4);
    int mx, my, mz2, mw2;
    if (kind == 1) {
        int4 m4 = *(const int4*)((const int*)mask + drow + tid * 4);
        mx = m4.x != 0; my = m4.y != 0; mz2 = m4.z != 0; mw2 = m4.w != 0;
    } else if (kind == 2) {
        float4 m4 = *(const float4*)((const float*)mask + drow + tid * 4);
        mx = m4.x != 0.f; my = m4.y != 0.f; mz2 = m4.z != 0.f; mw2 = m4.w != 0.f;
    } else {
        uchar4 m4 = *(const uchar4*)((const unsigned char*)mask + drow + tid * 4);
        mx = m4.x; my = m4.y; mz2 = m4.z; mw2 = m4.w;
    }
    v.x = (v.x + dv.x) * 0.125f;
    v.y = (v.y + dv.y) * 0.125f;
    v.z = (v.z + dv.z) * 0.125f;
    v.w = (v.w + dv.w) * 0.125f;
    if (mx)  v.x = -CUDART_INF_F;
    if (my)  v.y = -CUDART_INF_F;
    if (mz2) v.z = -CUDART_INF_F;
    if (mw2) v.w = -CUDART_INF_F;

    float m = fmaxf(fmaxf(v.x, v.y), fmaxf(v.z, v.w));
#pragma unroll
    for (int o = 16; o > 0; o >>= 1)
        m = fmaxf(m, __shfl_xor_sync(0xffffffffu, m, o));
    if ((tid & 31) == 0) redm[tid >> 5] = m;
    __syncthreads();
    float rowmax = redm[0];
#pragma unroll
    for (int i = 1; i < 8; i++) rowmax = fmaxf(rowmax, redm[i]);

    v.x = __expf(v.x - rowmax);
    v.y = __expf(v.y - rowmax);
    v.z = __expf(v.z - rowmax);
    v.w = __expf(v.w - rowmax);

    float s = v.x + v.y + v.z + v.w;
#pragma unroll
    for (int o = 16; o > 0; o >>= 1)
        s += __shfl_xor_sync(0xffffffffu, s, o);
    if ((tid & 31) == 0) reds[tid >> 5] = s;
    __syncthreads();
    float rowsum = 0.f;
#pragma unroll
    for (int i = 0; i < 8; i++) rowsum += reds[i];

    const float inv = 1.0f / rowsum;
    v.x *= inv; v.y *= inv; v.z *= inv; v.w *= inv;
    *(float4*)(P + prow + tid * 4) = v;
}

// ===========================================================================
// Kernel 3 (WMMA bf16 split-3): out = P @ V.  Tile 64(n) x 64(d), K=1024.
// 128 threads = 4 warps. (Unchanged this round — profiled as launch #4.)
// ===========================================================================
#define S3_PHI 0
#define S3_PLO 9216
#define S3_VHI 18432
#define S3_VLO 27648
#define S3_TOTAL 36864
#define S3_LDA 68

__global__ __launch_bounds__(128) void k_pv_w(
    const float* __restrict__ P, float* __restrict__ out)
{
    extern __shared__ char sm[];
    __nv_bfloat16* Phi = (__nv_bfloat16*)(sm + S3_PHI);
    __nv_bfloat16* Plo = (__nv_bfloat16*)(sm + S3_PLO);
    __nv_bfloat16* Vhi = (__nv_bfloat16*)(sm + S3_VHI);
    __nv_bfloat16* Vlo = (__nv_bfloat16*)(sm + S3_VLO);
    float* accbuf = (float*)sm;

    const int n0 = blockIdx.x * 64;
    const int z  = blockIdx.y;         // h*8 + b
    const int h  = z >> 3;
    const int b  = z & 7;
    const int tid = threadIdx.x;
    const int wid = tid >> 5;

    const float* Pb = P + ((size_t)z * Nk + n0) * Nk;

    wmma::fragment<wmma::accumulator, 16, 16, 16, float> acc[4];
#pragma unroll
    for (int nt = 0; nt < 4; nt++) wmma::fill_fragment(acc[nt], 0.0f);

    for (int m0 = 0; m0 < Nk; m0 += 64) {
        for (int idx = tid; idx < 64 * 16; idx += 128) {
            const int r  = idx >> 4;
            const int c4 = (idx & 15) * 4;
            float4 v = *(const float4*)(Pb + (size_t)r * Nk + m0 + c4);
            __nv_bfloat16 hx = __float2bfloat16(v.x);
            __nv_bfloat16 hy = __float2bfloat16(v.y);
            __nv_bfloat16 hz = __float2bfloat16(v.z);
            __nv_bfloat16 hw = __float2bfloat16(v.w);
            __nv_bfloat162 h01(hx, hy), h23(hz, hw);
            __nv_bfloat162 l01(__float2bfloat16(v.x - __bfloat162float(hx)),
                               __float2bfloat16(v.y - __bfloat162float(hy)));
            __nv_bfloat162 l23(__float2bfloat16(v.z - __bfloat162float(hz)),
                               __float2bfloat16(v.w - __bfloat162float(hw)));
            __nv_bfloat162* ph = (__nv_bfloat162*)(Phi + r * LDT + c4);
            __nv_bfloat162* pl = (__nv_bfloat162*)(Plo + r * LDT + c4);
            ph[0] = h01; ph[1] = h23;
            pl[0] = l01; pl[1] = l23;
        }
        for (int idx = tid; idx < 64 * 8; idx += 128) {
            const int r = idx >> 3;
            const int u = idx & 7;
            const size_t gv = ((size_t)b * Nk + m0 + r) * Ck + h * Dk + u * 8;
            *(uint4*)(Vhi + r * LDT + u * 8) = *(const uint4*)(g_vhi + gv);
            *(uint4*)(Vlo + r * LDT + u * 8) = *(const uint4*)(g_vlo + gv);
        }
        __syncthreads();

        const __nv_bfloat16* Ab[3] = {Phi, Phi, Plo};
        const __nv_bfloat16* Bb[3] = {Vhi, Vlo, Vhi};
#pragma unroll
        for (int p = 0; p < 3; p++) {
#pragma unroll
            for (int kt = 0; kt < 4; kt++) {
                wmma::fragment<wmma::matrix_a, 16, 16, 16, __nv_bfloat16, wmma::row_major> a;
                wmma::load_matrix_sync(a, Ab[p] + (wid * 16) * LDT + kt * 16, LDT);
#pragma unroll
                for (int nt = 0; nt < 4; nt++) {
                    wmma::fragment<wmma::matrix_b, 16, 16, 16, __nv_bfloat16, wmma::row_major> bf;
                    wmma::load_matrix_sync(bf, Bb[p] + (kt * 16) * LDT + nt * 16, LDT);
                    wmma::mma_sync(acc[nt], a, bf, acc[nt]);
                }
            }
        }
        __syncthreads();
    }

#pragma unroll
    for (int nt = 0; nt < 4; nt++)
        wmma::store_matrix_sync(accbuf + (wid * 16) * S3_LDA + nt * 16, acc[nt],
                                S3_LDA, wmma::mem_row_major);
    __syncthreads();

    for (int idx = tid; idx < 64 * 16; idx += 128) {
        const int r  = idx >> 4;
        const int c4 = (idx & 15) * 4;
        float4 o = *(const float4*)(accbuf + r * S3_LDA + c4);
        *(float4*)(out + ((size_t)b * Nk + n0 + r) * Ck + h * Dk + c4) = o;
    }
}

// ---------------------------------------------------------------------------
extern "C" void kernel_launch(void* const* d_in, const int* in_sizes, int n_in,
                              void* d_out, int out_size)
{
    (void)in_sizes; (void)n_in; (void)out_size;

    const float* q    = (const float*)d_in[0];
    const float* kmat = (const float*)d_in[1];
    const float* vmat = (const float*)d_in[2];
    const void*  mask = d_in[3];
    const float* dis  = (const float*)d_in[4];

    float* out  = (float*)d_out;              // [8,1024,256]
    float* Pbuf = (float*)d_out + OUT_ELEMS;  // [4,8,1024,1024]

    static int attr_set = 0;
    if (!attr_set) {
        cudaFuncSetAttribute(k_qk,
            cudaFuncAttributeMaxDynamicSharedMemorySize, QK_TOTAL);
        cudaFuncSetAttribute(k_pv_w,
            cudaFuncAttributeMaxDynamicSharedMemorySize, S3_TOTAL);
        attr_set = 1;
    }

    // Launch order: pv is launch #4 (profiler window).
    dim3 gc((OUT_ELEMS / 4 + 255) / 256, 3);
    k_cvt_all<<<gc, 256>>>(q, kmat, vmat);

    dim3 g1(Nk / 64, Nk / 64, Hk * Bk);
    k_qk<<<g1, 128, QK_TOTAL>>>(Pbuf);

    k_softmax_f<<<Hk * Bk * Nk, 256>>>(Pbuf, dis, mask);

    dim3 g3(Nk / 64, Hk * Bk);
    k_pv_w<<<g3, 128, S3_TOTAL>>>(Pbuf, out);
}